// round 2
// baseline (speedup 1.0000x reference)
#include <cuda_runtime.h>
#include <math.h>

#define BB 2
#define DD 1024
#define LL 4096
#define FSZ 4
#define NDEPTH 11
#define PADN 3072   // (FS-1) * max_dilation = 3*1024

// Scratch (allocation-free rule: __device__ globals)
__device__ float g_y[BB * DD * LL];
__device__ float g_z[BB * DD * LL];

// ---------------------------------------------------------------------------
// Kernel 1: fused 11-level dilated causal depthwise conv chain + gated sum
// One CTA per (b, c) row. Row lives in SMEM with zero apron in front.
// ---------------------------------------------------------------------------
__global__ __launch_bounds__(512) void conv_chain_kernel(
    const float* __restrict__ x,
    const float* __restrict__ h0,
    const float* __restrict__ h1)
{
    __shared__ float a_sh[PADN + LL];
    const int row = blockIdx.x;            // b*DD + c
    const int c   = row & (DD - 1);
    const int tid = threadIdx.x;

    float f0[FSZ], f1[FSZ];
#pragma unroll
    for (int t = 0; t < FSZ; t++) {
        f0[t] = h0[c * FSZ + t];
        f1[t] = h1[c * FSZ + t];
    }

    // zero apron + load x row
    for (int i = tid; i < PADN; i += 512) a_sh[i] = 0.0f;
    const float* xr = x + (size_t)row * LL;
#pragma unroll
    for (int k = 0; k < 8; k++) a_sh[PADN + tid + k * 512] = xr[tid + k * 512];
    __syncthreads();

    float yacc[8], bprev[8];
#pragma unroll
    for (int k = 0; k < 8; k++) { yacc[k] = 0.0f; bprev[k] = 0.0f; }

    int dil = 1;
#pragma unroll 1
    for (int d = 0; d < NDEPTH; d++) {
        float anew[8], bcur[8];
#pragma unroll
        for (int k = 0; k < 8; k++) {
            const int base = PADN + tid + k * 512;
            float s0 = 0.0f, s1 = 0.0f;
#pragma unroll
            for (int t = 0; t < FSZ; t++) {
                const float v = a_sh[base - dil * (FSZ - 1 - t)];
                s0 = fmaf(f0[t], v, s0);
                s1 = fmaf(f1[t], v, s1);
            }
            anew[k] = s0;
            bcur[k] = s1;
        }
        // y += sigmoid(a_list[d]) * b_list[d-1], d = 1..10; d==1 term counted twice
        if (d >= 1) {
            const float mult = (d == 1) ? 2.0f : 1.0f;
#pragma unroll
            for (int k = 0; k < 8; k++) {
                const float sg = 1.0f / (1.0f + expf(-anew[k]));
                yacc[k] = fmaf(mult * sg, bprev[k], yacc[k]);
            }
        }
#pragma unroll
        for (int k = 0; k < 8; k++) bprev[k] = bcur[k];
        __syncthreads();                // all reads of a_sh done
        if (d < NDEPTH - 1) {
#pragma unroll
            for (int k = 0; k < 8; k++) a_sh[PADN + tid + k * 512] = anew[k];
            __syncthreads();            // writes visible for next depth
        }
        dil <<= 1;
    }

    float* yr = g_y + (size_t)row * LL;
#pragma unroll
    for (int k = 0; k < 8; k++) yr[tid + k * 512] = yacc[k];
}

// ---------------------------------------------------------------------------
// Kernel 2: z[b,o,l] = sum_c W[o,c] * y[b,c,l] + bias[o] + x[b,o,l]
// Classic 128x128x8 fp32 SIMT GEMM, 256 threads, 8x8 per thread.
// ---------------------------------------------------------------------------
#define GBM 128
#define GBN 128
#define GBK 8

__global__ __launch_bounds__(256) void mix_gemm_kernel(
    const float* __restrict__ W,     // DD x DD row-major (o, c)
    const float* __restrict__ bias,  // DD
    const float* __restrict__ x)     // BB x DD x LL
{
    __shared__ float As[GBK][GBM];
    __shared__ float Bs[GBK][GBN];

    const int bn = blockIdx.x, bm = blockIdx.y, b = blockIdx.z;
    const int m0 = bm * GBM, n0 = bn * GBN;
    const float* Bmat = g_y + (size_t)b * DD * LL;

    const int tid  = threadIdx.x;
    const int tx   = tid & 15;       // 0..15 -> 8 cols each
    const int ty   = tid >> 4;       // 0..15 -> 8 rows each
    const int arow = tid >> 1, acol = (tid & 1) * 4;
    const int brow = tid >> 5, bcol = (tid & 31) * 4;

    float acc[8][8];
#pragma unroll
    for (int i = 0; i < 8; i++)
#pragma unroll
        for (int j = 0; j < 8; j++) acc[i][j] = 0.0f;

#pragma unroll 1
    for (int k0 = 0; k0 < DD; k0 += GBK) {
        const float4 av = *(const float4*)&W[(size_t)(m0 + arow) * DD + k0 + acol];
        As[acol + 0][arow] = av.x;
        As[acol + 1][arow] = av.y;
        As[acol + 2][arow] = av.z;
        As[acol + 3][arow] = av.w;
        const float4 bv = *(const float4*)&Bmat[(size_t)(k0 + brow) * LL + n0 + bcol];
        *(float4*)&Bs[brow][bcol] = bv;
        __syncthreads();

#pragma unroll
        for (int k = 0; k < GBK; k++) {
            float af[8], bf[8];
            *(float4*)&af[0] = *(const float4*)&As[k][ty * 8 + 0];
            *(float4*)&af[4] = *(const float4*)&As[k][ty * 8 + 4];
            *(float4*)&bf[0] = *(const float4*)&Bs[k][tx * 8 + 0];
            *(float4*)&bf[4] = *(const float4*)&Bs[k][tx * 8 + 4];
#pragma unroll
            for (int i = 0; i < 8; i++)
#pragma unroll
                for (int j = 0; j < 8; j++)
                    acc[i][j] = fmaf(af[i], bf[j], acc[i][j]);
        }
        __syncthreads();
    }

    // epilogue: + bias + residual x, store to g_z
    float* Z = g_z + (size_t)b * DD * LL;
    const float* X = x + (size_t)b * DD * LL;
#pragma unroll
    for (int i = 0; i < 8; i++) {
        const int m = m0 + ty * 8 + i;
        const float bo = bias[m];
#pragma unroll
        for (int j = 0; j < 8; j += 4) {
            const int n = n0 + tx * 8 + j;
            const size_t off = (size_t)m * LL + n;
            const float4 xv = *(const float4*)&X[off];
            float4 zv;
            zv.x = acc[i][j + 0] + bo + xv.x;
            zv.y = acc[i][j + 1] + bo + xv.y;
            zv.z = acc[i][j + 2] + bo + xv.z;
            zv.w = acc[i][j + 3] + bo + xv.w;
            *(float4*)&Z[off] = zv;
        }
    }
}

// ---------------------------------------------------------------------------
// Kernel 3: LayerNorm over channel dim per (b, l).
// CTA: 256 threads = 32 l-columns x 8 o-groups. Two passes over z (L2-hot).
// ---------------------------------------------------------------------------
__global__ __launch_bounds__(256) void ln_kernel(
    const float* __restrict__ gamma,
    const float* __restrict__ beta,
    float* __restrict__ out)
{
    const int b  = blockIdx.y;
    const int l0 = blockIdx.x * 32;
    const int lx = threadIdx.x & 31;
    const int oy = threadIdx.x >> 5;   // 0..7
    const int l  = l0 + lx;

    const float* Z = g_z + (size_t)b * DD * LL;

    float s = 0.0f, ss = 0.0f;
    for (int o = oy; o < DD; o += 8) {
        const float v = Z[(size_t)o * LL + l];
        s  += v;
        ss += v * v;
    }

    __shared__ float sbuf[8][32];
    __shared__ float ssbuf[8][32];
    __shared__ float mu_s[32];
    __shared__ float rstd_s[32];
    sbuf[oy][lx]  = s;
    ssbuf[oy][lx] = ss;
    __syncthreads();
    if (oy == 0) {
        float ts = 0.0f, tss = 0.0f;
#pragma unroll
        for (int r = 0; r < 8; r++) { ts += sbuf[r][lx]; tss += ssbuf[r][lx]; }
        const float mu  = ts * (1.0f / DD);
        const float var = tss * (1.0f / DD) - mu * mu;
        mu_s[lx]   = mu;
        rstd_s[lx] = rsqrtf(var + 1e-5f);
    }
    __syncthreads();
    const float mu = mu_s[lx], rstd = rstd_s[lx];

    float* O = out + (size_t)b * DD * LL;
    for (int o = oy; o < DD; o += 8) {
        const size_t off = (size_t)o * LL + l;
        O[off] = (Z[off] - mu) * rstd * gamma[o] + beta[o];
    }
}

// ---------------------------------------------------------------------------
extern "C" void kernel_launch(void* const* d_in, const int* in_sizes, int n_in,
                              void* d_out, int out_size) {
    const float* x     = (const float*)d_in[0];
    const float* h0    = (const float*)d_in[1];
    const float* h1    = (const float*)d_in[2];
    const float* w     = (const float*)d_in[3];
    const float* bias  = (const float*)d_in[4];
    const float* gamma = (const float*)d_in[5];
    const float* beta  = (const float*)d_in[6];
    float* out = (float*)d_out;

    conv_chain_kernel<<<BB * DD, 512>>>(x, h0, h1);

    dim3 gg(LL / GBN, DD / GBM, BB);
    mix_gemm_kernel<<<gg, 256>>>(w, bias, x);

    ln_kernel<<<dim3(LL / 32, BB), 256>>>(gamma, beta, out);
}

// round 16
// speedup vs baseline: 2.9065x; 2.9065x over previous
#include <cuda_runtime.h>
#include <cuda_bf16.h>
#include <cstdint>
#include <math.h>

#define BB 2
#define DD 1024
#define LL 4096
#define FSZ 4
#define NDEPTH 11
#define PADN 3072   // (FS-1) * max_dilation = 3*1024

// ---------------------------------------------------------------------------
// Scratch (allocation-free rule: __device__ globals)
// ---------------------------------------------------------------------------
__device__ __align__(16) float g_y[BB * DD * LL];                  // conv output  [b][c][l]
__device__ __align__(16) float g_z[BB * DD * LL];                  // pre-LN       [b][o][l]
__device__ __align__(16) __nv_bfloat16 g_yT_hi[BB * LL * DD];      // yT hi        [b][l][c]
__device__ __align__(16) __nv_bfloat16 g_yT_lo[BB * LL * DD];      // yT lo
__device__ __align__(16) __nv_bfloat16 g_w_hi[DD * DD];            // W hi         [o][c]
__device__ __align__(16) __nv_bfloat16 g_w_lo[DD * DD];            // W lo

__device__ __forceinline__ uint32_t smem_u32(const void* p) {
    uint32_t a;
    asm("{ .reg .u64 t; cvta.to.shared.u64 t, %1; cvt.u32.u64 %0, t; }" : "=r"(a) : "l"(p));
    return a;
}

// ---------------------------------------------------------------------------
// Kernel 1: fused 11-level dilated causal depthwise conv chain + gated sum.
// v2: 8 contiguous elements/thread -> 2x LDS.128 per tap. (unchanged)
// ---------------------------------------------------------------------------
__global__ __launch_bounds__(512) void conv_chain_kernel(
    const float* __restrict__ x,
    const float* __restrict__ h0,
    const float* __restrict__ h1)
{
    __shared__ float a_sh[PADN + LL];
    const int row = blockIdx.x;            // b*DD + c
    const int c   = row & (DD - 1);
    const int tid = threadIdx.x;
    const int base = PADN + tid * 8;       // base%8 == 0

    float f0[FSZ], f1[FSZ];
#pragma unroll
    for (int t = 0; t < FSZ; t++) {
        f0[t] = h0[c * FSZ + t];
        f1[t] = h1[c * FSZ + t];
    }

    for (int i = tid; i < PADN / 4; i += 512) ((float4*)a_sh)[i] = make_float4(0.f, 0.f, 0.f, 0.f);
    {
        const float4* x4 = (const float4*)(x + (size_t)row * LL);
        *(float4*)&a_sh[base]     = x4[tid * 2];
        *(float4*)&a_sh[base + 4] = x4[tid * 2 + 1];
    }
    __syncthreads();

    float yacc[8], bprev[8];
#pragma unroll
    for (int k = 0; k < 8; k++) { yacc[k] = 0.0f; bprev[k] = 0.0f; }

#pragma unroll
    for (int d = 0; d < NDEPTH; d++) {
        const int dil = 1 << d;
        float s0[8], s1[8];
#pragma unroll
        for (int k = 0; k < 8; k++) { s0[k] = 0.0f; s1[k] = 0.0f; }

        if (d < 2) {
            float w[16];
            *(float4*)&w[0]  = *(const float4*)&a_sh[base - 8];
            *(float4*)&w[4]  = *(const float4*)&a_sh[base - 4];
            *(float4*)&w[8]  = *(const float4*)&a_sh[base];
            *(float4*)&w[12] = *(const float4*)&a_sh[base + 4];
#pragma unroll
            for (int t = 0; t < FSZ; t++) {
#pragma unroll
                for (int k = 0; k < 8; k++) {
                    const float v = w[8 + k - dil * (FSZ - 1 - t)];
                    s0[k] = fmaf(f0[t], v, s0[k]);
                    s1[k] = fmaf(f1[t], v, s1[k]);
                }
            }
        } else {
#pragma unroll
            for (int t = 0; t < FSZ; t++) {
                const float* p = &a_sh[base - dil * (FSZ - 1 - t)];
                float tv[8];
                *(float4*)&tv[0] = *(const float4*)p;
                *(float4*)&tv[4] = *(const float4*)(p + 4);
#pragma unroll
                for (int k = 0; k < 8; k++) {
                    s0[k] = fmaf(f0[t], tv[k], s0[k]);
                    s1[k] = fmaf(f1[t], tv[k], s1[k]);
                }
            }
        }

        if (d >= 1) {
            const float mult = (d == 1) ? 2.0f : 1.0f;
#pragma unroll
            for (int k = 0; k < 8; k++) {
                const float sg = __fdividef(1.0f, 1.0f + __expf(-s0[k]));
                yacc[k] = fmaf(mult * sg, bprev[k], yacc[k]);
            }
        }
#pragma unroll
        for (int k = 0; k < 8; k++) bprev[k] = s1[k];
        __syncthreads();
        if (d < NDEPTH - 1) {
            *(float4*)&a_sh[base]     = *(float4*)&s0[0];
            *(float4*)&a_sh[base + 4] = *(float4*)&s0[4];
            __syncthreads();
        }
    }

    float* yr = g_y + (size_t)row * LL + tid * 8;
    *(float4*)&yr[0] = *(float4*)&yacc[0];
    *(float4*)&yr[4] = *(float4*)&yacc[4];
}

// ---------------------------------------------------------------------------
// Kernel 2a: W -> bf16 hi/lo split (unchanged)
// ---------------------------------------------------------------------------
__global__ __launch_bounds__(256) void wsplit_kernel(const float* __restrict__ W) {
    const int idx = blockIdx.x * 256 + threadIdx.x;
    const float4 v = ((const float4*)W)[idx];
    float a[4] = {v.x, v.y, v.z, v.w};
    __nv_bfloat16 h[4], l[4];
#pragma unroll
    for (int j = 0; j < 4; j++) {
        h[j] = __float2bfloat16(a[j]);
        l[j] = __float2bfloat16(a[j] - __bfloat162float(h[j]));
    }
    union { __nv_bfloat162 b2[2]; uint2 u; } ph, pl;
    ph.b2[0] = __halves2bfloat162(h[0], h[1]);
    ph.b2[1] = __halves2bfloat162(h[2], h[3]);
    pl.b2[0] = __halves2bfloat162(l[0], l[1]);
    pl.b2[1] = __halves2bfloat162(l[2], l[3]);
    ((uint2*)g_w_hi)[idx] = ph.u;
    ((uint2*)g_w_lo)[idx] = pl.u;
}

// ---------------------------------------------------------------------------
// Kernel 2b: y[b][c][l] -> yT_hi/lo[b][l][c] (unchanged)
// ---------------------------------------------------------------------------
__global__ __launch_bounds__(256) void transpose_split_kernel() {
    __shared__ float tile[32][33];
    const int b  = blockIdx.z;
    const int c0 = blockIdx.y * 32;
    const int l0 = blockIdx.x * 32;
    const int tid = threadIdx.x;
    const int tx = tid & 31, ty = tid >> 5;

    const float* Y = g_y + ((size_t)b * DD + c0) * LL + l0;
#pragma unroll
    for (int r = 0; r < 4; r++) {
        const int cc = ty + r * 8;
        tile[cc][tx] = Y[(size_t)cc * LL + tx];
    }
    __syncthreads();

    const int ll = tid >> 3;
    const int cq = (tid & 7) * 4;
    __nv_bfloat16 h[4], l[4];
#pragma unroll
    for (int j = 0; j < 4; j++) {
        const float v = tile[cq + j][ll];
        h[j] = __float2bfloat16(v);
        l[j] = __float2bfloat16(v - __bfloat162float(h[j]));
    }
    union { __nv_bfloat162 b2[2]; uint2 u; } ph, pl;
    ph.b2[0] = __halves2bfloat162(h[0], h[1]);
    ph.b2[1] = __halves2bfloat162(h[2], h[3]);
    pl.b2[0] = __halves2bfloat162(l[0], l[1]);
    pl.b2[1] = __halves2bfloat162(l[2], l[3]);
    const size_t off = ((size_t)b * LL + (l0 + ll)) * DD + c0 + cq;
    *(uint2*)(g_yT_hi + off) = ph.u;
    *(uint2*)(g_yT_lo + off) = pl.u;
}

// ---------------------------------------------------------------------------
// Kernel 3: split-bf16 GEMM via mma.sync.m16n8k16 (base sm_103 — no 'a' gate)
// z[b,o,l] = sum_c W[o,c] y[b,c,l] + bias[o] + x[b,o,l]
// CTA 128x128, 8 warps (4m x 2n, warp tile 32x64), K chunks of 64.
// SMEM tiles XOR-swizzled (col16 ^= row&7) for conflict-free ldmatrix.
// ---------------------------------------------------------------------------
#define TILE_BYTES 16384                       // 128 rows x 128 B
#define SMEM_GEMM (4 * TILE_BYTES)             // Ah, Al, Bh, Bl = 64 KB

__device__ __forceinline__ uint32_t sw_off(int row, int col16) {
    return (uint32_t)(row * 128 + ((col16 ^ (row & 7)) << 4));
}

#define LDMATRIX_X4(r0, r1, r2, r3, addr) \
    asm volatile("ldmatrix.sync.aligned.m8n8.x4.shared.b16 {%0,%1,%2,%3}, [%4];" \
        : "=r"(r0), "=r"(r1), "=r"(r2), "=r"(r3) : "r"(addr))

#define MMA_BF16(c, a, b0, b1) \
    asm volatile("mma.sync.aligned.m16n8k16.row.col.f32.bf16.bf16.f32 " \
        "{%0,%1,%2,%3}, {%4,%5,%6,%7}, {%8,%9}, {%0,%1,%2,%3};" \
        : "+f"((c)[0]), "+f"((c)[1]), "+f"((c)[2]), "+f"((c)[3]) \
        : "r"((a)[0]), "r"((a)[1]), "r"((a)[2]), "r"((a)[3]), "r"(b0), "r"(b1))

__global__ __launch_bounds__(256) void mix_gemm_mma(
    const float* __restrict__ bias,
    const float* __restrict__ x)
{
    extern __shared__ char smem[];
    const uint32_t sb = smem_u32(smem);
    const int tid  = threadIdx.x;
    const int wid  = tid >> 5, lane = tid & 31;
    const int bn = blockIdx.x, bm = blockIdx.y, b = blockIdx.z;
    const int m0 = bm * 128, n0 = bn * 128;
    const int wm = (wid >> 1) * 32;    // warp m offset: 0,32,64,96
    const int wn = (wid & 1) * 64;     // warp n offset: 0,64

    char* sAh = smem;
    char* sAl = smem + TILE_BYTES;
    char* sBh = smem + 2 * TILE_BYTES;
    char* sBl = smem + 3 * TILE_BYTES;
    const uint32_t uAh = sb, uAl = sb + TILE_BYTES,
                   uBh = sb + 2 * TILE_BYTES, uBl = sb + 3 * TILE_BYTES;

    const __nv_bfloat16* __restrict__ Agh = g_w_hi + (size_t)m0 * DD;
    const __nv_bfloat16* __restrict__ Agl = g_w_lo + (size_t)m0 * DD;
    const __nv_bfloat16* __restrict__ Bgh = g_yT_hi + ((size_t)b * LL + n0) * DD;
    const __nv_bfloat16* __restrict__ Bgl = g_yT_lo + ((size_t)b * LL + n0) * DD;

    float acc[2][8][4];
#pragma unroll
    for (int i = 0; i < 2; i++)
#pragma unroll
        for (int j = 0; j < 8; j++)
#pragma unroll
            for (int k = 0; k < 4; k++) acc[i][j][k] = 0.0f;

#pragma unroll 1
    for (int ck = 0; ck < DD / 64; ck++) {
        const int k0 = ck * 64;
        // stage 4 tiles: 128 rows x 64 bf16 each; 16B chunk per (row, col16)
#pragma unroll
        for (int i = 0; i < 4; i++) {
            const int idx = tid + i * 256;
            const int row = idx >> 3, c16 = idx & 7;
            const size_t goff = (size_t)row * DD + k0 + c16 * 8;
            const uint32_t so = sw_off(row, c16);
            *(uint4*)(sAh + so) = *(const uint4*)(Agh + goff);
            *(uint4*)(sAl + so) = *(const uint4*)(Agl + goff);
            *(uint4*)(sBh + so) = *(const uint4*)(Bgh + goff);
            *(uint4*)(sBl + so) = *(const uint4*)(Bgl + goff);
        }
        __syncthreads();

#pragma unroll
        for (int ks = 0; ks < 4; ks++) {
            // A fragments: 2 m16 frags, hi+lo
            uint32_t ah[2][4], al[2][4];
#pragma unroll
            for (int mf = 0; mf < 2; mf++) {
                const int r   = wm + mf * 16 + (lane & 15);
                const int c16 = ks * 2 + (lane >> 4);
                const uint32_t so = sw_off(r, c16);
                LDMATRIX_X4(ah[mf][0], ah[mf][1], ah[mf][2], ah[mf][3], uAh + so);
                LDMATRIX_X4(al[mf][0], al[mf][1], al[mf][2], al[mf][3], uAl + so);
            }
            // B: 4 n16 groups; each x4 = two n8 frags (b0,b1),(b2,b3)
#pragma unroll
            for (int g = 0; g < 4; g++) {
                const int q = lane >> 3, lr = lane & 7;
                const int n   = wn + g * 16 + ((q >> 1) << 3) + lr;
                const int c16 = ks * 2 + (q & 1);
                const uint32_t so = sw_off(n, c16);
                uint32_t bh[4], bl[4];
                LDMATRIX_X4(bh[0], bh[1], bh[2], bh[3], uBh + so);
                LDMATRIX_X4(bl[0], bl[1], bl[2], bl[3], uBl + so);
#pragma unroll
                for (int mf = 0; mf < 2; mf++) {
                    MMA_BF16(acc[mf][g * 2 + 0], ah[mf], bh[0], bh[1]);
                    MMA_BF16(acc[mf][g * 2 + 0], ah[mf], bl[0], bl[1]);
                    MMA_BF16(acc[mf][g * 2 + 0], al[mf], bh[0], bh[1]);
                    MMA_BF16(acc[mf][g * 2 + 1], ah[mf], bh[2], bh[3]);
                    MMA_BF16(acc[mf][g * 2 + 1], ah[mf], bl[2], bl[3]);
                    MMA_BF16(acc[mf][g * 2 + 1], al[mf], bh[2], bh[3]);
                }
            }
        }
        __syncthreads();
    }

    // epilogue: acc(m16n8): c0,c1 -> row g=lane>>2, cols (lane&3)*2..+1; c2,c3 -> row g+8
#pragma unroll
    for (int mf = 0; mf < 2; mf++) {
        const int rbase = m0 + wm + mf * 16 + (lane >> 2);
#pragma unroll
        for (int half = 0; half < 2; half++) {
            const int m = rbase + half * 8;
            const float bo = bias[m];
            const float* X = x   + ((size_t)b * DD + m) * LL;
            float*       Z = g_z + ((size_t)b * DD + m) * LL;
#pragma unroll
            for (int nf = 0; nf < 8; nf++) {
                const int n = n0 + wn + nf * 8 + (lane & 3) * 2;
                const float2 xv = *(const float2*)&X[n];
                float2 zv;
                zv.x = acc[mf][nf][half * 2 + 0] + bo + xv.x;
                zv.y = acc[mf][nf][half * 2 + 1] + bo + xv.y;
                *(float2*)&Z[n] = zv;
            }
        }
    }
}

// ---------------------------------------------------------------------------
// Kernel 4: LayerNorm over channel dim per (b, l).  (unchanged)
// ---------------------------------------------------------------------------
__global__ __launch_bounds__(256) void ln_kernel(
    const float* __restrict__ gamma,
    const float* __restrict__ beta,
    float* __restrict__ out)
{
    const int b  = blockIdx.y;
    const int l0 = blockIdx.x * 32;
    const int lx = threadIdx.x & 31;
    const int oy = threadIdx.x >> 5;
    const int l  = l0 + lx;

    const float* Z = g_z + (size_t)b * DD * LL;

    float s = 0.0f, ss = 0.0f;
    for (int o = oy; o < DD; o += 8) {
        const float v = Z[(size_t)o * LL + l];
        s  += v;
        ss += v * v;
    }

    __shared__ float sbuf[8][32];
    __shared__ float ssbuf[8][32];
    __shared__ float mu_s[32];
    __shared__ float rstd_s[32];
    sbuf[oy][lx]  = s;
    ssbuf[oy][lx] = ss;
    __syncthreads();
    if (oy == 0) {
        float ts = 0.0f, tss = 0.0f;
#pragma unroll
        for (int r = 0; r < 8; r++) { ts += sbuf[r][lx]; tss += ssbuf[r][lx]; }
        const float mu  = ts * (1.0f / DD);
        const float var = tss * (1.0f / DD) - mu * mu;
        mu_s[lx]   = mu;
        rstd_s[lx] = rsqrtf(var + 1e-5f);
    }
    __syncthreads();
    const float mu = mu_s[lx], rstd = rstd_s[lx];

    float* O = out + (size_t)b * DD * LL;
    for (int o = oy; o < DD; o += 8) {
        const size_t off = (size_t)o * LL + l;
        O[off] = (Z[off] - mu) * rstd * gamma[o] + beta[o];
    }
}

// ---------------------------------------------------------------------------
extern "C" void kernel_launch(void* const* d_in, const int* in_sizes, int n_in,
                              void* d_out, int out_size) {
    const float* x     = (const float*)d_in[0];
    const float* h0    = (const float*)d_in[1];
    const float* h1    = (const float*)d_in[2];
    const float* w     = (const float*)d_in[3];
    const float* bias  = (const float*)d_in[4];
    const float* gamma = (const float*)d_in[5];
    const float* beta  = (const float*)d_in[6];
    float* out = (float*)d_out;

    conv_chain_kernel<<<BB * DD, 512>>>(x, h0, h1);
    wsplit_kernel<<<DD * DD / 4 / 256, 256>>>(w);
    transpose_split_kernel<<<dim3(LL / 32, DD / 32, BB), 256>>>();

    cudaFuncSetAttribute(mix_gemm_mma, cudaFuncAttributeMaxDynamicSharedMemorySize, SMEM_GEMM);
    mix_gemm_mma<<<dim3(LL / 128, DD / 128, BB), 256, SMEM_GEMM>>>(bias, x);

    ln_kernel<<<dim3(LL / 32, BB), 256>>>(gamma, beta, out);
}